// round 14
// baseline (speedup 1.0000x reference)
#include <cuda_runtime.h>
#include <cuda_bf16.h>
#include <cuda_fp16.h>
#include <cstdint>

#define NCTA  128
#define BDIM  256
#define LATD  512
#define HIDD  1024
#define NSTEPS 20

// A chunk image: 128 rows x 72 halfs (144 B padded rows) = 18432 B, K-chunk 64
#define A_CH     9216             // elems per chunk image
#define SRC_BAND (8 * A_CH)       // K=512  -> 8 chunks
#define ACT_BAND (16 * A_CH)      // K=1024 -> 16 chunks
#define A_BYTES  18432u
#define NRING    4

// smem layout (bytes): W1 resident | W2 resident | A ring x4
#define SW1   0u
#define SW1_STRIDE 1040           // 512*2 + 16 pad  (4 words mod 32 -> conflict-free)
#define SW2   66560u
#define SW2_STRIDE 2064           // 1024*2 + 16 pad
#define SA    132608u
#define SMEM_TOTAL (132608u + 4u * A_BYTES)   // 206336

// ---------------- persistent device state ----------------
__device__ __align__(16) __half g_srcs[8 * SRC_BAND];   // GEMM1 A images [band][ch]
__device__ __align__(16) __half g_acts[8 * ACT_BAND];   // GEMM2 A images
__device__ float g_h [1024 * LATD];
__device__ float g_rk[1024 * LATD];
__device__ unsigned g_ctr = 0, g_seq = 0;
__device__ unsigned g_bctr[64], g_bseq[64];

// ---------------- helpers ----------------
__device__ __forceinline__ uint32_t smem_u32(const void* p) {
    uint32_t a;
    asm("{ .reg .u64 t; cvta.to.shared.u64 t, %1; cvt.u32.u64 %0, t; }" : "=r"(a) : "l"(p));
    return a;
}
__device__ __forceinline__ void mma_f16(float* c, const unsigned* a, unsigned b0, unsigned b1) {
    asm volatile(
        "mma.sync.aligned.m16n8k16.row.col.f32.f16.f16.f32 "
        "{%0,%1,%2,%3}, {%4,%5,%6,%7}, {%8,%9}, {%0,%1,%2,%3};"
        : "+f"(c[0]), "+f"(c[1]), "+f"(c[2]), "+f"(c[3])
        : "r"(a[0]), "r"(a[1]), "r"(a[2]), "r"(a[3]), "r"(b0), "r"(b1));
}
__device__ __forceinline__ void ldsm_x4(unsigned* r, uint32_t addr) {
    asm volatile("ldmatrix.sync.aligned.m8n8.x4.shared.b16 {%0,%1,%2,%3}, [%4];"
                 : "=r"(r[0]), "=r"(r[1]), "=r"(r[2]), "=r"(r[3]) : "r"(addr));
}
__device__ __forceinline__ float fast_tanh(float x) {
    float e = __expf(2.0f * x);
    return 1.0f - __fdividef(2.0f, e + 1.0f);
}
__device__ __forceinline__ unsigned pack_h(float a, float b) {
    __half2 h = __floats2half2_rn(a, b);
    return *(unsigned*)&h;
}
typedef unsigned long long ull;
__device__ __forceinline__ ull pack2(float v) {
    ull r; asm("mov.b64 %0, {%1, %1};" : "=l"(r) : "r"(__float_as_uint(v))); return r;
}
__device__ __forceinline__ void ffma2(ull &d, ull a, ull b) {
    asm("fma.rn.f32x2 %0, %1, %2, %0;" : "+l"(d) : "l"(a), "l"(b));
}
__device__ __forceinline__ void unpack2(ull v, float &lo, float &hi) {
    unsigned a, b; asm("mov.b64 {%0, %1}, %2;" : "=r"(a), "=r"(b) : "l"(v));
    lo = __uint_as_float(a); hi = __uint_as_float(b);
}
__device__ __forceinline__ void mbar_init(uint32_t a, uint32_t n) {
    asm volatile("mbarrier.init.shared.b64 [%0], %1;" :: "r"(a), "r"(n) : "memory");
}
__device__ __forceinline__ void mbar_wait(uint32_t a, uint32_t par) {
    asm volatile(
        "{\n\t.reg .pred P;\n\tW%=:\n\t"
        "mbarrier.try_wait.parity.acquire.cta.shared::cta.b64 P, [%0], %1, 0x989680;\n\t"
        "@P bra.uni D%=;\n\tbra.uni W%=;\n\tD%=:\n\t}"
        :: "r"(a), "r"(par) : "memory");
}

// ---- lightweight cross-CTA barriers ----
__device__ __forceinline__ void barrier_core(unsigned* ctr, unsigned* seq,
                                             unsigned last, unsigned target) {
    __syncthreads();
    if (threadIdx.x == 0) {
        unsigned p;
        asm volatile("atom.acq_rel.gpu.global.add.u32 %0, [%1], 1;"
                     : "=r"(p) : "l"(ctr) : "memory");
        if (p == last) {
            asm volatile("st.relaxed.gpu.global.u32 [%0], 0;" :: "l"(ctr) : "memory");
            asm volatile("red.release.gpu.global.add.u32 [%0], 1;" :: "l"(seq) : "memory");
        } else {
            unsigned v;
            for (;;) {
                asm volatile("ld.acquire.gpu.global.u32 %0, [%1];" : "=r"(v) : "l"(seq) : "memory");
                if (v >= target) break;
                __nanosleep(20);
            }
        }
    }
    __syncthreads();
}
__device__ __forceinline__ void gridbar(unsigned target) {
    barrier_core(&g_ctr, &g_seq, NCTA - 1, target);
}
__device__ __forceinline__ void bandbar(int band, unsigned target) {
    barrier_core(&g_bctr[band * 8], &g_bseq[band * 8], 15, target);
}

// ---------------- cooperative GEMM: fp16 mma.sync, resident W, ring-4 depth-3 A stream ----
// A ring slot: 128 rows x 144 B (fp16, K-chunk 64). W resident rows: WSTRIDE bytes.
// NFRAG = B 8-col frags per warp (4 -> NB=64, 2 -> NB=32).
template<int NFRAG, int NCH, int WSTRIDE>
__device__ __forceinline__ void gemm_tc(
    uint32_t ringbase, uint32_t wbase, const uint32_t* mbs, int* ph,
    const __half* __restrict__ Ast,      // band image base (chunk stride A_CH elems)
    float C[2][4][4])
{
    const int tid = threadIdx.x;
    const int lane = tid & 31, wrp = tid >> 5;
    const int wm = wrp >> 1, wn = wrp & 1;

    #pragma unroll
    for (int f = 0; f < 2; f++)
        #pragma unroll
        for (int nf = 0; nf < NFRAG; nf++)
            #pragma unroll
            for (int c = 0; c < 4; c++) C[f][nf][c] = 0.0f;

    // ldmatrix per-lane offsets (144B-row layout validated R7-R9)
    const uint32_t aoff = (uint32_t)((wm * 32 + (lane & 15)) * 144 + (lane >> 4) * 16);
    uint32_t boff[2];
    #pragma unroll
    for (int grp = 0; grp < NFRAG / 2; grp++)
        boff[grp] = wbase +
            (uint32_t)((wn * (8 * NFRAG) + grp * 16 + (lane & 15)) * WSTRIDE + (lane >> 4) * 16);

    auto issue = [&](int kc) {
        if (kc < NCH && tid == 0) {
            int slot = kc & (NRING - 1);
            uint32_t mb = mbs[slot];
            uint32_t sb = ringbase + (uint32_t)slot * A_BYTES;
            asm volatile("mbarrier.arrive.expect_tx.shared.b64 _, [%0], %1;"
                         :: "r"(mb), "r"(A_BYTES) : "memory");
            asm volatile(
                "cp.async.bulk.shared::cta.global.mbarrier::complete_tx::bytes [%0], [%1], %2, [%3];"
                :: "r"(sb), "l"(Ast + (size_t)kc * A_CH), "r"(A_BYTES), "r"(mb) : "memory");
        }
    };

    issue(0); issue(1); issue(2);
    for (int kc = 0; kc < NCH; kc++) {
        int slot = kc & (NRING - 1);
        mbar_wait(mbs[slot], (uint32_t)ph[slot]);
        ph[slot] ^= 1;
        __syncthreads();          // all threads done computing kc-1 -> slot (kc+3)%4 free
        issue(kc + 3);

        uint32_t sb = ringbase + (uint32_t)slot * A_BYTES;
        uint32_t bk = (uint32_t)(kc * 128);      // 64 k * 2 B into resident W rows
        #pragma unroll
        for (int ks = 0; ks < 4; ks++) {
            unsigned ah[2][4], bh[2][4];
            #pragma unroll
            for (int f = 0; f < 2; f++)
                ldsm_x4(ah[f], sb + aoff + f * 2304 + ks * 32);
            #pragma unroll
            for (int grp = 0; grp < NFRAG / 2; grp++)
                ldsm_x4(bh[grp], boff[grp] + bk + ks * 32);
            #pragma unroll
            for (int f = 0; f < 2; f++)
                #pragma unroll
                for (int nf = 0; nf < NFRAG; nf++) {
                    int grp = nf >> 1, p = nf & 1;
                    mma_f16(C[f][nf], ah[f], bh[grp][p], bh[grp][p + 2]);
                }
        }
    }
}

// ---------------- the persistent kernel ----------------
extern "C" __global__ void __launch_bounds__(BDIM, 1)
ode_tc(const float* __restrict__ x,     const float* __restrict__ W_in,
       const float* __restrict__ b_in,  const float* __restrict__ W1,
       const float* __restrict__ b1,    const float* __restrict__ W2,
       const float* __restrict__ b2,    const float* __restrict__ W_out,
       const float* __restrict__ b_out, float* __restrict__ out)
{
    extern __shared__ __align__(1024) unsigned char dyn[];
    __shared__ float sb1[64], sw1r[64], sb2[32];
    __shared__ __align__(8) ull s_mb[NRING];
    __shared__ uint32_t s_mbaddr[NRING];

    const int tid  = threadIdx.x;
    const int lane = tid & 31, wrp = tid >> 5;
    const int wm = wrp >> 1, wn = wrp & 1;
    const int g = lane >> 2, ws = lane & 3;
    const int bid = blockIdx.x;
    const int mt  = bid >> 4, nt = bid & 15;
    const int m0  = mt * 128, n0 = nt * 64, j0 = nt * 32;
    const uint32_t sdyn = smem_u32(dyn);
    int ph[NRING] = {0, 0, 0, 0};

    unsigned base_gseq = *(volatile unsigned*)&g_seq;
    unsigned base_bseq = *(volatile unsigned*)&g_bseq[mt * 8];
    unsigned bnbar = 0;

    if (tid < NRING) {
        uint32_t a = smem_u32(&s_mb[tid]);
        mbar_init(a, 1);
        s_mbaddr[tid] = a;
    }
    if (tid < 64) {
        sb1[tid]  = b1[n0 + tid];
        sw1r[tid] = W1[(size_t)LATD * HIDD + n0 + tid];   // t-row of W1
    }
    if (tid < 32) sb2[tid] = b2[j0 + tid];

    // ---- h0 = tanh(x @ W_in + b_in) for this CTA's 8 rows (fp32 SIMT), uses dyn scratch ----
    {
        float* xT = (float*)dyn;                       // [256][10]
        int r0 = bid * 8;
        for (int i = tid; i < 2048; i += BDIM) {
            int f = i & 255, rr = i >> 8;
            xT[f * 10 + rr] = x[(size_t)(r0 + rr) * 256 + f];
        }
        __syncthreads();
        int band = bid >> 4;
        int mloc0 = (bid & 15) * 8;
        #pragma unroll
        for (int half = 0; half < 2; half++) {
            int j = tid + half * 256;
            ull acc[4];
            #pragma unroll
            for (int p = 0; p < 4; p++) acc[p] = 0ull;
            #pragma unroll 4
            for (int k = 0; k < 256; k++) {
                ull wp = pack2(W_in[(size_t)k * LATD + j]);
                #pragma unroll
                for (int p = 0; p < 4; p++) {
                    ull a = *(const ull*)(xT + k * 10 + 2 * p);
                    ffma2(acc[p], a, wp);
                }
            }
            float bj = b_in[j];
            #pragma unroll
            for (int p = 0; p < 4; p++) {
                float lo, hi; unpack2(acc[p], lo, hi);
                float v0 = fast_tanh(lo + bj), v1 = fast_tanh(hi + bj);
                #pragma unroll
                for (int q = 0; q < 2; q++) {
                    int m = r0 + 2 * p + q;
                    float val = q ? v1 : v0;
                    g_h[(size_t)m * LATD + j] = val;
                    size_t adr = (size_t)band * SRC_BAND + (size_t)(j >> 6) * A_CH
                               + (size_t)(mloc0 + 2 * p + q) * 72 + (j & 63);
                    g_srcs[adr] = __float2half(val);
                }
            }
        }
        __syncthreads();
    }

    // ---- fill resident W tiles in smem (fp16), once per launch ----
    for (int i = tid; i < 64 * 512; i += BDIM) {
        int n = i >> 9, k = i & 511;
        *(__half*)(dyn + SW1 + n * SW1_STRIDE + k * 2) =
            __float2half(W1[(size_t)k * HIDD + n0 + n]);
    }
    for (int i = tid; i < 32 * 1024; i += BDIM) {
        int n = i >> 10, k = i & 1023;
        *(__half*)(dyn + SW2 + n * SW2_STRIDE + k * 2) =
            __float2half(W2[(size_t)k * LATD + j0 + n]);
    }
    __syncthreads();
    gridbar(base_gseq + 1);          // h0 images visible everywhere

    const float dt = 1.0f / NSTEPS;
    float C[2][4][4];

    for (int step = 0; step < NSTEPS; step++) {
        float t = dt * step;
        #pragma unroll 1
        for (int stage = 0; stage < 4; stage++) {
            float ts = t + ((stage == 0) ? 0.0f : (stage == 3) ? dt : 0.5f * dt);

            // ==== GEMM1: z = src @ W1  (tile 128x64, K=512, 8 chunks) ====
            gemm_tc<4, 8, SW1_STRIDE>(sdyn + SA, sdyn + SW1, s_mbaddr, ph,
                                      g_srcs + (size_t)mt * SRC_BAND, C);
            #pragma unroll
            for (int f = 0; f < 2; f++)
                #pragma unroll
                for (int nf = 0; nf < 4; nf++) {
                    int nl = wn * 32 + nf * 8 + 2 * ws;
                    float bb0 = sb1[nl]     + ts * sw1r[nl];
                    float bb1 = sb1[nl + 1] + ts * sw1r[nl + 1];
                    #pragma unroll
                    for (int hr = 0; hr < 2; hr++) {
                        float a0 = fast_tanh(C[f][nf][hr * 2]     + bb0);
                        float a1 = fast_tanh(C[f][nf][hr * 2 + 1] + bb1);
                        int mloc = wm * 32 + f * 16 + g + hr * 8;
                        int ng = n0 + nl;
                        size_t adr = (size_t)mt * ACT_BAND + (size_t)(ng >> 6) * A_CH
                                   + (size_t)mloc * 72 + (ng & 63);
                        ((unsigned*)g_acts)[adr >> 1] = pack_h(a0, a1);
                    }
                }
            bandbar(mt, base_bseq + (++bnbar));

            // ==== GEMM2: k = act @ W2  (tile 128x32, K=1024, 16 chunks) ====
            gemm_tc<2, 16, SW2_STRIDE>(sdyn + SA, sdyn + SW2, s_mbaddr, ph,
                                       g_acts + (size_t)mt * ACT_BAND, C);
            #pragma unroll
            for (int f = 0; f < 2; f++)
                #pragma unroll
                for (int nf = 0; nf < 2; nf++) {
                    int nl = wn * 16 + nf * 8 + 2 * ws;
                    #pragma unroll
                    for (int hr = 0; hr < 2; hr++) {
                        int mloc = wm * 32 + f * 16 + g + hr * 8;
                        int m = m0 + mloc;
                        float kk0 = C[f][nf][hr * 2]     + sb2[nl];
                        float kk1 = C[f][nf][hr * 2 + 1] + sb2[nl + 1];
                        float* hp = g_h  + (size_t)m * LATD + j0 + nl;
                        float* rp = g_rk + (size_t)m * LATD + j0 + nl;
                        float2 hv = *(const float2*)hp;
                        float sv0, sv1;
                        if (stage == 0) {
                            float2 rv; rv.x = kk0; rv.y = kk1;
                            *(float2*)rp = rv;
                            sv0 = hv.x + 0.5f * dt * kk0; sv1 = hv.y + 0.5f * dt * kk1;
                        } else if (stage == 1) {
                            float2 rv = *(const float2*)rp;
                            rv.x += 2.0f * kk0; rv.y += 2.0f * kk1;
                            *(float2*)rp = rv;
                            sv0 = hv.x + 0.5f * dt * kk0; sv1 = hv.y + 0.5f * dt * kk1;
                        } else if (stage == 2) {
                            float2 rv = *(const float2*)rp;
                            rv.x += 2.0f * kk0; rv.y += 2.0f * kk1;
                            *(float2*)rp = rv;
                            sv0 = hv.x + dt * kk0; sv1 = hv.y + dt * kk1;
                        } else {
                            float2 rv = *(const float2*)rp;
                            sv0 = hv.x + (dt / 6.0f) * (rv.x + kk0);
                            sv1 = hv.y + (dt / 6.0f) * (rv.y + kk1);
                            float2 nh; nh.x = sv0; nh.y = sv1;
                            *(float2*)hp = nh;
                        }
                        int jg = j0 + nl;
                        size_t adr = (size_t)mt * SRC_BAND + (size_t)(jg >> 6) * A_CH
                                   + (size_t)mloc * 72 + (jg & 63);
                        ((unsigned*)g_srcs)[adr >> 1] = pack_h(sv0, sv1);
                    }
                }
            bandbar(mt, base_bseq + (++bnbar));
        }
    }

    // ---- out = h[:, :256] @ W_out + b_out for this CTA's 8 rows ----
    {
        float* sh = (float*)dyn;               // [8][256] scratch (W no longer needed)
        int r0 = bid * 8;
        for (int i = tid; i < 2048; i += BDIM) {
            int f = i & 255, rr = i >> 8;
            sh[rr * 256 + f] = g_h[(size_t)(r0 + rr) * LATD + f];
        }
        __syncthreads();
        int m = tid >> 5, o0 = (tid & 31) * 2;
        float s0 = 0.0f, s1 = 0.0f;
        #pragma unroll 4
        for (int k = 0; k < 256; k++) {
            float hv = sh[m * 256 + k];
            float2 w = *(const float2*)(W_out + (size_t)k * 64 + o0);
            s0 = fmaf(hv, w.x, s0);
            s1 = fmaf(hv, w.y, s1);
        }
        float2 o;
        o.x = s0 + b_out[o0];
        o.y = s1 + b_out[o0 + 1];
        *(float2*)(out + (size_t)(r0 + m) * 64 + o0) = o;
    }
}

extern "C" void kernel_launch(void* const* d_in, const int* in_sizes, int n_in,
                              void* d_out, int out_size)
{
    const float* x     = (const float*)d_in[0];
    const float* W_in  = (const float*)d_in[1];
    const float* b_in  = (const float*)d_in[2];
    const float* W1    = (const float*)d_in[3];
    const float* b1    = (const float*)d_in[4];
    const float* W2    = (const float*)d_in[5];
    const float* b2    = (const float*)d_in[6];
    const float* W_out = (const float*)d_in[7];
    const float* b_out = (const float*)d_in[8];

    static bool attr_done = false;
    if (!attr_done) {
        cudaFuncSetAttribute(ode_tc, cudaFuncAttributeMaxDynamicSharedMemorySize, (int)SMEM_TOTAL);
        attr_done = true;
    }
    ode_tc<<<NCTA, BDIM, SMEM_TOTAL>>>(x, W_in, b_in, W1, b1, W2, b2, W_out, b_out,
                                       (float*)d_out);
}

// round 15
// speedup vs baseline: 1.0269x; 1.0269x over previous
#include <cuda_runtime.h>
#include <cuda_bf16.h>
#include <cuda_fp16.h>
#include <cstdint>

#define NCTA  128
#define BDIM  512
#define LATD  512
#define HIDD  1024
#define NSTEPS 20

// A chunk image: 128 rows x 136 halfs (272 B padded rows) = 34816 B, K-chunk 128
#define A_CH     17408            // elems per chunk image
#define SRC_BAND (4 * A_CH)       // K=512  -> 4 chunks
#define ACT_BAND (8 * A_CH)       // K=1024 -> 8 chunks
#define A_BYTES  34816u

// smem layout (bytes): W1 resident | W2 resident | A ring x2
#define SW1   0u
#define SW1_STRIDE 1040           // 512*2 + 16 pad  (4 words mod 32 -> conflict-free)
#define SW2   66560u
#define SW2_STRIDE 2064           // 1024*2 + 16 pad
#define SA    132608u
#define SMEM_TOTAL (132608u + 2u * A_BYTES)   // 202240

// ---------------- persistent device state ----------------
__device__ __align__(16) __half g_srcs[8 * SRC_BAND];   // GEMM1 A images [band][ch]
__device__ __align__(16) __half g_acts[8 * ACT_BAND];   // GEMM2 A images
__device__ float g_h [1024 * LATD];
__device__ float g_rk[1024 * LATD];
__device__ unsigned g_ctr = 0, g_seq = 0;
__device__ unsigned g_bctr[64], g_bseq[64];

// ---------------- helpers ----------------
__device__ __forceinline__ uint32_t smem_u32(const void* p) {
    uint32_t a;
    asm("{ .reg .u64 t; cvta.to.shared.u64 t, %1; cvt.u32.u64 %0, t; }" : "=r"(a) : "l"(p));
    return a;
}
__device__ __forceinline__ void mma_f16(float* c, const unsigned* a, unsigned b0, unsigned b1) {
    asm volatile(
        "mma.sync.aligned.m16n8k16.row.col.f32.f16.f16.f32 "
        "{%0,%1,%2,%3}, {%4,%5,%6,%7}, {%8,%9}, {%0,%1,%2,%3};"
        : "+f"(c[0]), "+f"(c[1]), "+f"(c[2]), "+f"(c[3])
        : "r"(a[0]), "r"(a[1]), "r"(a[2]), "r"(a[3]), "r"(b0), "r"(b1));
}
__device__ __forceinline__ void ldsm_x4(unsigned* r, uint32_t addr) {
    asm volatile("ldmatrix.sync.aligned.m8n8.x4.shared.b16 {%0,%1,%2,%3}, [%4];"
                 : "=r"(r[0]), "=r"(r[1]), "=r"(r[2]), "=r"(r[3]) : "r"(addr));
}
__device__ __forceinline__ float fast_tanh(float x) {
    float e = __expf(2.0f * x);
    return 1.0f - __fdividef(2.0f, e + 1.0f);
}
__device__ __forceinline__ unsigned pack_h(float a, float b) {
    __half2 h = __floats2half2_rn(a, b);
    return *(unsigned*)&h;
}
typedef unsigned long long ull;
__device__ __forceinline__ ull pack2(float v) {
    ull r; asm("mov.b64 %0, {%1, %1};" : "=l"(r) : "r"(__float_as_uint(v))); return r;
}
__device__ __forceinline__ void ffma2(ull &d, ull a, ull b) {
    asm("fma.rn.f32x2 %0, %1, %2, %0;" : "+l"(d) : "l"(a), "l"(b));
}
__device__ __forceinline__ void unpack2(ull v, float &lo, float &hi) {
    unsigned a, b; asm("mov.b64 {%0, %1}, %2;" : "=r"(a), "=r"(b) : "l"(v));
    lo = __uint_as_float(a); hi = __uint_as_float(b);
}
__device__ __forceinline__ void mbar_init(uint32_t a, uint32_t n) {
    asm volatile("mbarrier.init.shared.b64 [%0], %1;" :: "r"(a), "r"(n) : "memory");
}
__device__ __forceinline__ void mbar_wait(uint32_t a, uint32_t par) {
    asm volatile(
        "{\n\t.reg .pred P;\n\tW%=:\n\t"
        "mbarrier.try_wait.parity.acquire.cta.shared::cta.b64 P, [%0], %1, 0x989680;\n\t"
        "@P bra.uni D%=;\n\tbra.uni W%=;\n\tD%=:\n\t}"
        :: "r"(a), "r"(par) : "memory");
}

// ---- lightweight cross-CTA barriers ----
__device__ __forceinline__ void barrier_core(unsigned* ctr, unsigned* seq,
                                             unsigned last, unsigned target) {
    __syncthreads();
    if (threadIdx.x == 0) {
        unsigned p;
        asm volatile("atom.acq_rel.gpu.global.add.u32 %0, [%1], 1;"
                     : "=r"(p) : "l"(ctr) : "memory");
        if (p == last) {
            asm volatile("st.relaxed.gpu.global.u32 [%0], 0;" :: "l"(ctr) : "memory");
            asm volatile("red.release.gpu.global.add.u32 [%0], 1;" :: "l"(seq) : "memory");
        } else {
            unsigned v;
            for (;;) {
                asm volatile("ld.acquire.gpu.global.u32 %0, [%1];" : "=r"(v) : "l"(seq) : "memory");
                if (v >= target) break;
                __nanosleep(20);
            }
        }
    }
    __syncthreads();
}
__device__ __forceinline__ void gridbar(unsigned target) {
    barrier_core(&g_ctr, &g_seq, NCTA - 1, target);
}
__device__ __forceinline__ void bandbar(int band, unsigned target) {
    barrier_core(&g_bctr[band * 8], &g_bseq[band * 8], 15, target);
}

// ---------------- cooperative GEMM: fp16 mma.sync, resident W, streamed A, 16 warps ----
// A ring slot: 128 rows x 272 B (fp16, K-chunk 128). W resident rows: WSTRIDE bytes.
// Warp grid 8x2: warp tile 16 rows x (8*NFRAG) cols. NFRAG=4 -> NB=64, NFRAG=2 -> NB=32.
template<int NFRAG, int NCH, int WSTRIDE>
__device__ __forceinline__ void gemm_tc(
    uint32_t ringbase, uint32_t wbase, uint32_t mb0, uint32_t mb1, int* ph,
    const __half* __restrict__ Ast,      // band image base (chunk stride A_CH elems)
    float C[4][4])
{
    const int tid = threadIdx.x;
    const int lane = tid & 31, wrp = tid >> 5;
    const int wm = wrp >> 1, wn = wrp & 1;

    #pragma unroll
    for (int nf = 0; nf < NFRAG; nf++)
        #pragma unroll
        for (int c = 0; c < 4; c++) C[nf][c] = 0.0f;

    const uint32_t aoff = (uint32_t)((wm * 16 + (lane & 15)) * 272 + (lane >> 4) * 16);
    uint32_t boff[2];
    #pragma unroll
    for (int grp = 0; grp < NFRAG / 2; grp++)
        boff[grp] = wbase +
            (uint32_t)((wn * (8 * NFRAG) + grp * 16 + (lane & 15)) * WSTRIDE + (lane >> 4) * 16);

    auto issue = [&](int kc) {
        if (kc < NCH && tid == 0) {
            uint32_t mb = (kc & 1) ? mb1 : mb0;
            uint32_t sb = ringbase + (uint32_t)(kc & 1) * A_BYTES;
            asm volatile("mbarrier.arrive.expect_tx.shared.b64 _, [%0], %1;"
                         :: "r"(mb), "r"(A_BYTES) : "memory");
            asm volatile(
                "cp.async.bulk.shared::cta.global.mbarrier::complete_tx::bytes [%0], [%1], %2, [%3];"
                :: "r"(sb), "l"(Ast + (size_t)kc * A_CH), "r"(A_BYTES), "r"(mb) : "memory");
        }
    };

    issue(0);
    for (int kc = 0; kc < NCH; kc++) {
        int slot = kc & 1;
        mbar_wait(slot ? mb1 : mb0, (uint32_t)ph[slot]);
        ph[slot] ^= 1;
        __syncthreads();          // everyone done computing kc-1 (other slot)
        issue(kc + 1);            // refill other slot while we compute kc

        uint32_t sb = ringbase + (uint32_t)slot * A_BYTES;
        uint32_t bk = (uint32_t)(kc * 256);      // 128 k * 2 B into resident W rows
        #pragma unroll
        for (int ks = 0; ks < 8; ks++) {
            unsigned ah[4], bh[2][4];
            ldsm_x4(ah, sb + aoff + ks * 32);
            #pragma unroll
            for (int grp = 0; grp < NFRAG / 2; grp++)
                ldsm_x4(bh[grp], boff[grp] + bk + ks * 32);
            #pragma unroll
            for (int nf = 0; nf < NFRAG; nf++) {
                int grp = nf >> 1, p = nf & 1;
                mma_f16(C[nf], ah, bh[grp][p], bh[grp][p + 2]);
            }
        }
    }
}

// ---------------- the persistent kernel ----------------
extern "C" __global__ void __launch_bounds__(BDIM, 1)
ode_tc(const float* __restrict__ x,     const float* __restrict__ W_in,
       const float* __restrict__ b_in,  const float* __restrict__ W1,
       const float* __restrict__ b1,    const float* __restrict__ W2,
       const float* __restrict__ b2,    const float* __restrict__ W_out,
       const float* __restrict__ b_out, float* __restrict__ out)
{
    extern __shared__ __align__(1024) unsigned char dyn[];
    __shared__ float sb1[64], sw1r[64], sb2[32];
    __shared__ __align__(8) ull s_mb[2];

    const int tid  = threadIdx.x;
    const int lane = tid & 31, wrp = tid >> 5;
    const int wm = wrp >> 1, wn = wrp & 1;
    const int g = lane >> 2, ws = lane & 3;
    const int bid = blockIdx.x;
    const int mt  = bid >> 4, nt = bid & 15;
    const int m0  = mt * 128, n0 = nt * 64, j0 = nt * 32;
    const uint32_t sdyn = smem_u32(dyn);
    const uint32_t mb0 = smem_u32(&s_mb[0]), mb1 = smem_u32(&s_mb[1]);
    int ph[2] = {0, 0};

    unsigned base_gseq = *(volatile unsigned*)&g_seq;
    unsigned base_bseq = *(volatile unsigned*)&g_bseq[mt * 8];
    unsigned bnbar = 0;

    if (tid == 0) { mbar_init(mb0, 1); mbar_init(mb1, 1); }
    if (tid < 64) {
        sb1[tid]  = b1[n0 + tid];
        sw1r[tid] = W1[(size_t)LATD * HIDD + n0 + tid];   // t-row of W1
    }
    if (tid < 32) sb2[tid] = b2[j0 + tid];

    // ---- h0 = tanh(x @ W_in + b_in) for this CTA's 8 rows (fp32 SIMT), uses dyn scratch ----
    {
        float* xT = (float*)dyn;                       // [256][10]
        int r0 = bid * 8;
        for (int i = tid; i < 2048; i += BDIM) {
            int f = i & 255, rr = i >> 8;
            xT[f * 10 + rr] = x[(size_t)(r0 + rr) * 256 + f];
        }
        __syncthreads();
        int band = bid >> 4;
        int mloc0 = (bid & 15) * 8;
        int j = tid;                                   // 512 threads, one LAT column each
        ull acc[4];
        #pragma unroll
        for (int p = 0; p < 4; p++) acc[p] = 0ull;
        #pragma unroll 4
        for (int k = 0; k < 256; k++) {
            ull wp = pack2(W_in[(size_t)k * LATD + j]);
            #pragma unroll
            for (int p = 0; p < 4; p++) {
                ull a = *(const ull*)(xT + k * 10 + 2 * p);
                ffma2(acc[p], a, wp);
            }
        }
        float bj = b_in[j];
        #pragma unroll
        for (int p = 0; p < 4; p++) {
            float lo, hi; unpack2(acc[p], lo, hi);
            float v0 = fast_tanh(lo + bj), v1 = fast_tanh(hi + bj);
            #pragma unroll
            for (int q = 0; q < 2; q++) {
                int m = r0 + 2 * p + q;
                float val = q ? v1 : v0;
                g_h[(size_t)m * LATD + j] = val;
                size_t adr = (size_t)band * SRC_BAND + (size_t)(j >> 7) * A_CH
                           + (size_t)(mloc0 + 2 * p + q) * 136 + (j & 127);
                g_srcs[adr] = __float2half(val);
            }
        }
        __syncthreads();
    }

    // ---- fill resident W tiles in smem (fp16), once per launch ----
    for (int i = tid; i < 64 * 512; i += BDIM) {
        int n = i >> 9, k = i & 511;
        *(__half*)(dyn + SW1 + n * SW1_STRIDE + k * 2) =
            __float2half(W1[(size_t)k * HIDD + n0 + n]);
    }
    for (int i = tid; i < 32 * 1024; i += BDIM) {
        int n = i >> 10, k = i & 1023;
        *(__half*)(dyn + SW2 + n * SW2_STRIDE + k * 2) =
            __float2half(W2[(size_t)k * LATD + j0 + n]);
    }
    __syncthreads();
    gridbar(base_gseq + 1);          // h0 images visible everywhere

    const float dt = 1.0f / NSTEPS;
    float C[4][4];

    for (int step = 0; step < NSTEPS; step++) {
        float t = dt * step;
        #pragma unroll 1
        for (int stage = 0; stage < 4; stage++) {
            float ts = t + ((stage == 0) ? 0.0f : (stage == 3) ? dt : 0.5f * dt);

            // ==== GEMM1: z = src @ W1  (tile 128x64, K=512, 4 chunks) ====
            gemm_tc<4, 4, SW1_STRIDE>(sdyn + SA, sdyn + SW1, mb0, mb1, ph,
                                      g_srcs + (size_t)mt * SRC_BAND, C);
            #pragma unroll
            for (int nf = 0; nf < 4; nf++) {
                int nl = wn * 32 + nf * 8 + 2 * ws;
                float bb0 = sb1[nl]     + ts * sw1r[nl];
                float bb1 = sb1[nl + 1] + ts * sw1r[nl + 1];
                #pragma unroll
                for (int hr = 0; hr < 2; hr++) {
                    float a0 = fast_tanh(C[nf][hr * 2]     + bb0);
                    float a1 = fast_tanh(C[nf][hr * 2 + 1] + bb1);
                    int mloc = wm * 16 + g + hr * 8;
                    int ng = n0 + nl;
                    size_t adr = (size_t)mt * ACT_BAND + (size_t)(ng >> 7) * A_CH
                               + (size_t)mloc * 136 + (ng & 127);
                    ((unsigned*)g_acts)[adr >> 1] = pack_h(a0, a1);
                }
            }
            bandbar(mt, base_bseq + (++bnbar));

            // ==== GEMM2: k = act @ W2  (tile 128x32, K=1024, 8 chunks) ====
            gemm_tc<2, 8, SW2_STRIDE>(sdyn + SA, sdyn + SW2, mb0, mb1, ph,
                                      g_acts + (size_t)mt * ACT_BAND, C);
            #pragma unroll
            for (int nf = 0; nf < 2; nf++) {
                int nl = wn * 16 + nf * 8 + 2 * ws;
                #pragma unroll
                for (int hr = 0; hr < 2; hr++) {
                    int mloc = wm * 16 + g + hr * 8;
                    int m = m0 + mloc;
                    float kk0 = C[nf][hr * 2]     + sb2[nl];
                    float kk1 = C[nf][hr * 2 + 1] + sb2[nl + 1];
                    float* hp = g_h  + (size_t)m * LATD + j0 + nl;
                    float* rp = g_rk + (size_t)m * LATD + j0 + nl;
                    float2 hv = *(const float2*)hp;
                    float sv0, sv1;
                    if (stage == 0) {
                        float2 rv; rv.x = kk0; rv.y = kk1;
                        *(float2*)rp = rv;
                        sv0 = hv.x + 0.5f * dt * kk0; sv1 = hv.y + 0.5f * dt * kk1;
                    } else if (stage == 1) {
                        float2 rv = *(const float2*)rp;
                        rv.x += 2.0f * kk0; rv.y += 2.0f * kk1;
                        *(float2*)rp = rv;
                        sv0 = hv.x + 0.5f * dt * kk0; sv1 = hv.y + 0.5f * dt * kk1;
                    } else if (stage == 2) {
                        float2 rv = *(const float2*)rp;
                        rv.x += 2.0f * kk0; rv.y += 2.0f * kk1;
                        *(float2*)rp = rv;
                        sv0 = hv.x + dt * kk0; sv1 = hv.y + dt * kk1;
                    } else {
                        float2 rv = *(const float2*)rp;
                        sv0 = hv.x + (dt / 6.0f) * (rv.x + kk0);
                        sv1 = hv.y + (dt / 6.0f) * (rv.y + kk1);
                        float2 nh; nh.x = sv0; nh.y = sv1;
                        *(float2*)hp = nh;
                    }
                    int jg = j0 + nl;
                    size_t adr = (size_t)mt * SRC_BAND + (size_t)(jg >> 7) * A_CH
                               + (size_t)mloc * 136 + (jg & 127);
                    ((unsigned*)g_srcs)[adr >> 1] = pack_h(sv0, sv1);
                }
            }
            bandbar(mt, base_bseq + (++bnbar));
        }
    }

    // ---- out = h[:, :256] @ W_out + b_out for this CTA's 8 rows ----
    {
        float* sh = (float*)dyn;               // [8][256] scratch (W no longer needed)
        int r0 = bid * 8;
        for (int i = tid; i < 2048; i += BDIM) {
            int f = i & 255, rr = i >> 8;
            sh[rr * 256 + f] = g_h[(size_t)(r0 + rr) * LATD + f];
        }
        __syncthreads();
        int m = tid >> 6, o = tid & 63;
        float s = 0.0f;
        #pragma unroll 4
        for (int k = 0; k < 256; k++)
            s = fmaf(sh[m * 256 + k], W_out[(size_t)k * 64 + o], s);
        out[(size_t)(r0 + m) * 64 + o] = s + b_out[o];
    }
}

extern "C" void kernel_launch(void* const* d_in, const int* in_sizes, int n_in,
                              void* d_out, int out_size)
{
    const float* x     = (const float*)d_in[0];
    const float* W_in  = (const float*)d_in[1];
    const float* b_in  = (const float*)d_in[2];
    const float* W1    = (const float*)d_in[3];
    const float* b1    = (const float*)d_in[4];
    const float* W2    = (const float*)d_in[5];
    const float* b2    = (const float*)d_in[6];
    const float* W_out = (const float*)d_in[7];
    const float* b_out = (const float*)d_in[8];

    static bool attr_done = false;
    if (!attr_done) {
        cudaFuncSetAttribute(ode_tc, cudaFuncAttributeMaxDynamicSharedMemorySize, (int)SMEM_TOTAL);
        attr_done = true;
    }
    ode_tc<<<NCTA, BDIM, SMEM_TOTAL>>>(x, W_in, b_in, W1, b1, W2, b2, W_out, b_out,
                                       (float*)d_out);
}

// round 16
// speedup vs baseline: 1.0762x; 1.0480x over previous
#include <cuda_runtime.h>
#include <cuda_bf16.h>
#include <cuda_fp16.h>
#include <cstdint>

#define NCTA  128
#define BDIM  256
#define LATD  512
#define HIDD  1024
#define NSTEPS 20

// A chunk image: 128 rows x 136 halfs (272 B padded rows) = 34816 B
#define A_CH     17408            // elems per chunk image
#define SRC_BAND (4 * A_CH)       // K=512  -> 4 chunks
#define ACT_BAND (8 * A_CH)       // K=1024 -> 8 chunks
#define A_BYTES  34816u

// smem layout (bytes): W1 resident | W2 resident | A ring x2
#define SW1   0u
#define SW1_STRIDE 1040           // 512*2 + 16 pad  (4 words mod 32 -> conflict-free)
#define SW2   66560u
#define SW2_STRIDE 2064           // 1024*2 + 16 pad
#define SA    132608u
#define SMEM_TOTAL (132608u + 2u * A_BYTES)   // 202240

// ---------------- persistent device state ----------------
__device__ __align__(16) __half g_srcs[8 * SRC_BAND];   // GEMM1 A images [band][ch]
__device__ __align__(16) __half g_acts[8 * ACT_BAND];   // GEMM2 A images
__device__ float g_h [1024 * LATD];
__device__ float g_rk[1024 * LATD];
__device__ unsigned g_ctr = 0, g_seq = 0;
__device__ unsigned g_bctr[64], g_bseq[64];

// ---------------- helpers ----------------
__device__ __forceinline__ uint32_t smem_u32(const void* p) {
    uint32_t a;
    asm("{ .reg .u64 t; cvta.to.shared.u64 t, %1; cvt.u32.u64 %0, t; }" : "=r"(a) : "l"(p));
    return a;
}
__device__ __forceinline__ void mma_f16(float* c, const unsigned* a, unsigned b0, unsigned b1) {
    asm volatile(
        "mma.sync.aligned.m16n8k16.row.col.f32.f16.f16.f32 "
        "{%0,%1,%2,%3}, {%4,%5,%6,%7}, {%8,%9}, {%0,%1,%2,%3};"
        : "+f"(c[0]), "+f"(c[1]), "+f"(c[2]), "+f"(c[3])
        : "r"(a[0]), "r"(a[1]), "r"(a[2]), "r"(a[3]), "r"(b0), "r"(b1));
}
__device__ __forceinline__ void ldsm_x4(unsigned* r, uint32_t addr) {
    asm volatile("ldmatrix.sync.aligned.m8n8.x4.shared.b16 {%0,%1,%2,%3}, [%4];"
                 : "=r"(r[0]), "=r"(r[1]), "=r"(r[2]), "=r"(r[3]) : "r"(addr));
}
__device__ __forceinline__ float fast_tanh(float x) {
    float e = __expf(2.0f * x);
    return 1.0f - __fdividef(2.0f, e + 1.0f);
}
__device__ __forceinline__ unsigned pack_h(float a, float b) {
    __half2 h = __floats2half2_rn(a, b);
    return *(unsigned*)&h;
}
typedef unsigned long long ull;
__device__ __forceinline__ ull pack2(float v) {
    ull r; asm("mov.b64 %0, {%1, %1};" : "=l"(r) : "r"(__float_as_uint(v))); return r;
}
__device__ __forceinline__ void ffma2(ull &d, ull a, ull b) {
    asm("fma.rn.f32x2 %0, %1, %2, %0;" : "+l"(d) : "l"(a), "l"(b));
}
__device__ __forceinline__ void unpack2(ull v, float &lo, float &hi) {
    unsigned a, b; asm("mov.b64 {%0, %1}, %2;" : "=r"(a), "=r"(b) : "l"(v));
    lo = __uint_as_float(a); hi = __uint_as_float(b);
}
__device__ __forceinline__ void mbar_init(uint32_t a, uint32_t n) {
    asm volatile("mbarrier.init.shared.b64 [%0], %1;" :: "r"(a), "r"(n) : "memory");
}
__device__ __forceinline__ void mbar_wait(uint32_t a, uint32_t par) {
    asm volatile(
        "{\n\t.reg .pred P;\n\tW%=:\n\t"
        "mbarrier.try_wait.parity.acquire.cta.shared::cta.b64 P, [%0], %1, 0x989680;\n\t"
        "@P bra.uni D%=;\n\tbra.uni W%=;\n\tD%=:\n\t}"
        :: "r"(a), "r"(par) : "memory");
}

// ---- lightweight cross-CTA barriers ----
__device__ __forceinline__ void barrier_core(unsigned* ctr, unsigned* seq,
                                             unsigned last, unsigned target) {
    __syncthreads();
    if (threadIdx.x == 0) {
        unsigned p;
        asm volatile("atom.acq_rel.gpu.global.add.u32 %0, [%1], 1;"
                     : "=r"(p) : "l"(ctr) : "memory");
        if (p == last) {
            asm volatile("st.relaxed.gpu.global.u32 [%0], 0;" :: "l"(ctr) : "memory");
            asm volatile("red.release.gpu.global.add.u32 [%0], 1;" :: "l"(seq) : "memory");
        } else {
            unsigned v;
            for (;;) {
                asm volatile("ld.acquire.gpu.global.u32 %0, [%1];" : "=r"(v) : "l"(seq) : "memory");
                if (v >= target) break;
                __nanosleep(20);
            }
        }
    }
    __syncthreads();
}
__device__ __forceinline__ void gridbar(unsigned target) {
    barrier_core(&g_ctr, &g_seq, NCTA - 1, target);
}
__device__ __forceinline__ void bandbar(int band, unsigned target) {
    barrier_core(&g_bctr[band * 8], &g_bseq[band * 8], 15, target);
}

// ---------------- cooperative GEMM: fp16 mma.sync, resident W, streamed A ----------------
// A ring slot: 128 rows x 272 B (fp16, K-chunk 128). W resident rows: WSTRIDE bytes.
// NFRAG = B 8-col frags per warp (4 -> NB=64, 2 -> NB=32).
// ROT: per-CTA chunk-order rotation. Physical chunk pc=(kc+rot)%NCH desynchronizes the
// 16 band CTAs so they never demand the same gmem lines in the same burst.
template<int NFRAG, int NCH, int WSTRIDE>
__device__ __forceinline__ void gemm_tc(
    uint32_t ringbase, uint32_t wbase, uint32_t mb0, uint32_t mb1, int* ph, int rot,
    const __half* __restrict__ Ast,      // band image base (chunk stride A_CH elems)
    float C[2][4][4])
{
    const int tid = threadIdx.x;
    const int lane = tid & 31, wrp = tid >> 5;
    const int wm = wrp >> 1, wn = wrp & 1;

    #pragma unroll
    for (int f = 0; f < 2; f++)
        #pragma unroll
        for (int nf = 0; nf < NFRAG; nf++)
            #pragma unroll
            for (int c = 0; c < 4; c++) C[f][nf][c] = 0.0f;

    const uint32_t aoff = (uint32_t)((wm * 32 + (lane & 15)) * 272 + (lane >> 4) * 16);
    uint32_t boff[2];
    #pragma unroll
    for (int grp = 0; grp < NFRAG / 2; grp++)
        boff[grp] = wbase +
            (uint32_t)((wn * (8 * NFRAG) + grp * 16 + (lane & 15)) * WSTRIDE + (lane >> 4) * 16);

    auto issue = [&](int kc) {
        if (kc < NCH && tid == 0) {
            int pc = (kc + rot) & (NCH - 1);
            uint32_t mb = (kc & 1) ? mb1 : mb0;
            uint32_t sb = ringbase + (uint32_t)(kc & 1) * A_BYTES;
            asm volatile("mbarrier.arrive.expect_tx.shared.b64 _, [%0], %1;"
                         :: "r"(mb), "r"(A_BYTES) : "memory");
            asm volatile(
                "cp.async.bulk.shared::cta.global.mbarrier::complete_tx::bytes [%0], [%1], %2, [%3];"
                :: "r"(sb), "l"(Ast + (size_t)pc * A_CH), "r"(A_BYTES), "r"(mb) : "memory");
        }
    };

    issue(0);
    for (int kc = 0; kc < NCH; kc++) {
        int slot = kc & 1;
        int pc = (kc + rot) & (NCH - 1);
        mbar_wait(slot ? mb1 : mb0, (uint32_t)ph[slot]);
        ph[slot] ^= 1;
        __syncthreads();          // everyone done computing kc-1 (other slot)
        issue(kc + 1);            // refill other slot while we compute kc

        uint32_t sb = ringbase + (uint32_t)slot * A_BYTES;
        uint32_t bk = (uint32_t)(pc * 256);      // 128 k * 2 B into resident W rows
        #pragma unroll
        for (int ks = 0; ks < 8; ks++) {
            unsigned ah[2][4], bh[2][4];
            #pragma unroll
            for (int f = 0; f < 2; f++)
                ldsm_x4(ah[f], sb + aoff + f * 4352 + ks * 32);
            #pragma unroll
            for (int grp = 0; grp < NFRAG / 2; grp++)
                ldsm_x4(bh[grp], boff[grp] + bk + ks * 32);
            #pragma unroll
            for (int f = 0; f < 2; f++)
                #pragma unroll
                for (int nf = 0; nf < NFRAG; nf++) {
                    int grp = nf >> 1, p = nf & 1;
                    mma_f16(C[f][nf], ah[f], bh[grp][p], bh[grp][p + 2]);
                }
        }
    }
}

// ---------------- the persistent kernel ----------------
extern "C" __global__ void __launch_bounds__(BDIM, 1)
ode_tc(const float* __restrict__ x,     const float* __restrict__ W_in,
       const float* __restrict__ b_in,  const float* __restrict__ W1,
       const float* __restrict__ b1,    const float* __restrict__ W2,
       const float* __restrict__ b2,    const float* __restrict__ W_out,
       const float* __restrict__ b_out, float* __restrict__ out)
{
    extern __shared__ __align__(1024) unsigned char dyn[];
    __shared__ float sb1[64], sw1r[64], sb2[32];
    __shared__ __align__(8) ull s_mb[2];

    const int tid  = threadIdx.x;
    const int lane = tid & 31, wrp = tid >> 5;
    const int wm = wrp >> 1, wn = wrp & 1;
    const int g = lane >> 2, ws = lane & 3;
    const int bid = blockIdx.x;
    const int mt  = bid >> 4, nt = bid & 15;
    const int m0  = mt * 128, n0 = nt * 64, j0 = nt * 32;
    const uint32_t sdyn = smem_u32(dyn);
    const uint32_t mb0 = smem_u32(&s_mb[0]), mb1 = smem_u32(&s_mb[1]);
    int ph[2] = {0, 0};

    unsigned base_gseq = *(volatile unsigned*)&g_seq;
    unsigned base_bseq = *(volatile unsigned*)&g_bseq[mt * 8];
    unsigned bnbar = 0;

    if (tid == 0) { mbar_init(mb0, 1); mbar_init(mb1, 1); }
    if (tid < 64) {
        sb1[tid]  = b1[n0 + tid];
        sw1r[tid] = W1[(size_t)LATD * HIDD + n0 + tid];   // t-row of W1
    }
    if (tid < 32) sb2[tid] = b2[j0 + tid];

    // ---- h0 = tanh(x @ W_in + b_in) for this CTA's 8 rows (fp32 SIMT), uses dyn scratch ----
    {
        float* xT = (float*)dyn;                       // [256][10]
        int r0 = bid * 8;
        for (int i = tid; i < 2048; i += BDIM) {
            int f = i & 255, rr = i >> 8;
            xT[f * 10 + rr] = x[(size_t)(r0 + rr) * 256 + f];
        }
        __syncthreads();
        int band = bid >> 4;
        int mloc0 = (bid & 15) * 8;
        #pragma unroll
        for (int half = 0; half < 2; half++) {
            int j = tid + half * 256;
            ull acc[4];
            #pragma unroll
            for (int p = 0; p < 4; p++) acc[p] = 0ull;
            #pragma unroll 4
            for (int k = 0; k < 256; k++) {
                ull wp = pack2(W_in[(size_t)k * LATD + j]);
                #pragma unroll
                for (int p = 0; p < 4; p++) {
                    ull a = *(const ull*)(xT + k * 10 + 2 * p);
                    ffma2(acc[p], a, wp);
                }
            }
            float bj = b_in[j];
            #pragma unroll
            for (int p = 0; p < 4; p++) {
                float lo, hi; unpack2(acc[p], lo, hi);
                float v0 = fast_tanh(lo + bj), v1 = fast_tanh(hi + bj);
                #pragma unroll
                for (int q = 0; q < 2; q++) {
                    int m = r0 + 2 * p + q;
                    float val = q ? v1 : v0;
                    g_h[(size_t)m * LATD + j] = val;
                    size_t adr = (size_t)band * SRC_BAND + (size_t)(j >> 7) * A_CH
                               + (size_t)(mloc0 + 2 * p + q) * 136 + (j & 127);
                    g_srcs[adr] = __float2half(val);
                }
            }
        }
        __syncthreads();
    }

    // ---- fill resident W tiles in smem (fp16), once per launch ----
    for (int i = tid; i < 64 * 512; i += BDIM) {
        int n = i >> 9, k = i & 511;
        *(__half*)(dyn + SW1 + n * SW1_STRIDE + k * 2) =
            __float2half(W1[(size_t)k * HIDD + n0 + n]);
    }
    for (int i = tid; i < 32 * 1024; i += BDIM) {
        int n = i >> 10, k = i & 1023;
        *(__half*)(dyn + SW2 + n * SW2_STRIDE + k * 2) =
            __float2half(W2[(size_t)k * LATD + j0 + n]);
    }
    __syncthreads();
    gridbar(base_gseq + 1);          // h0 images visible everywhere

    const float dt = 1.0f / NSTEPS;
    float C[2][4][4];
    const int rot1 = nt & 3;         // GEMM1: 4 chunks
    const int rot2 = nt & 7;         // GEMM2: 8 chunks

    for (int step = 0; step < NSTEPS; step++) {
        float t = dt * step;
        #pragma unroll 1
        for (int stage = 0; stage < 4; stage++) {
            float ts = t + ((stage == 0) ? 0.0f : (stage == 3) ? dt : 0.5f * dt);

            // ==== GEMM1: z = src @ W1  (tile 128x64, K=512, 4 chunks, rotated) ====
            gemm_tc<4, 4, SW1_STRIDE>(sdyn + SA, sdyn + SW1, mb0, mb1, ph, rot1,
                                      g_srcs + (size_t)mt * SRC_BAND, C);
            #pragma unroll
            for (int f = 0; f < 2; f++)
                #pragma unroll
                for (int nf = 0; nf < 4; nf++) {
                    int nl = wn * 32 + nf * 8 + 2 * ws;
                    float bb0 = sb1[nl]     + ts * sw1r[nl];
                    float bb1 = sb1[nl + 1] + ts * sw1r[nl + 1];
                    #pragma unroll
                    for (int hr = 0; hr < 2; hr++) {
                        float a0 = fast_tanh(C[f][nf][hr * 2]     + bb0);
                        float a1 = fast_tanh(C[f][nf][hr * 2 + 1] + bb1);
                        int mloc = wm * 32 + f * 16 + g + hr * 8;
                        int ng = n0 + nl;
                        size_t adr = (size_t)mt * ACT_BAND + (size_t)(ng >> 7) * A_CH
                                   + (size_t)mloc * 136 + (ng & 127);
                        ((unsigned*)g_acts)[adr >> 1] = pack_h(a0, a1);
                    }
                }
            bandbar(mt, base_bseq + (++bnbar));

            // ==== GEMM2: k = act @ W2  (tile 128x32, K=1024, 8 chunks, rotated) ====
            gemm_tc<2, 8, SW2_STRIDE>(sdyn + SA, sdyn + SW2, mb0, mb1, ph, rot2,
                                      g_acts + (size_t)mt * ACT_BAND, C);
            #pragma unroll
            for (int f = 0; f < 2; f++)
                #pragma unroll
                for (int nf = 0; nf < 2; nf++) {
                    int nl = wn * 16 + nf * 8 + 2 * ws;
                    #pragma unroll
                    for (int hr = 0; hr < 2; hr++) {
                        int mloc = wm * 32 + f * 16 + g + hr * 8;
                        int m = m0 + mloc;
                        float kk0 = C[f][nf][hr * 2]     + sb2[nl];
                        float kk1 = C[f][nf][hr * 2 + 1] + sb2[nl + 1];
                        float* hp = g_h  + (size_t)m * LATD + j0 + nl;
                        float* rp = g_rk + (size_t)m * LATD + j0 + nl;
                        float2 hv = *(const float2*)hp;
                        float sv0, sv1;
                        if (stage == 0) {
                            float2 rv; rv.x = kk0; rv.y = kk1;
                            *(float2*)rp = rv;
                            sv0 = hv.x + 0.5f * dt * kk0; sv1 = hv.y + 0.5f * dt * kk1;
                        } else if (stage == 1) {
                            float2 rv = *(const float2*)rp;
                            rv.x += 2.0f * kk0; rv.y += 2.0f * kk1;
                            *(float2*)rp = rv;
                            sv0 = hv.x + 0.5f * dt * kk0; sv1 = hv.y + 0.5f * dt * kk1;
                        } else if (stage == 2) {
                            float2 rv = *(const float2*)rp;
                            rv.x += 2.0f * kk0; rv.y += 2.0f * kk1;
                            *(float2*)rp = rv;
                            sv0 = hv.x + dt * kk0; sv1 = hv.y + dt * kk1;
                        } else {
                            float2 rv = *(const float2*)rp;
                            sv0 = hv.x + (dt / 6.0f) * (rv.x + kk0);
                            sv1 = hv.y + (dt / 6.0f) * (rv.y + kk1);
                            float2 nh; nh.x = sv0; nh.y = sv1;
                            *(float2*)hp = nh;
                        }
                        int jg = j0 + nl;
                        size_t adr = (size_t)mt * SRC_BAND + (size_t)(jg >> 7) * A_CH
                                   + (size_t)mloc * 136 + (jg & 127);
                        ((unsigned*)g_srcs)[adr >> 1] = pack_h(sv0, sv1);
                    }
                }
            bandbar(mt, base_bseq + (++bnbar));
        }
    }

    // ---- out = h[:, :256] @ W_out + b_out for this CTA's 8 rows ----
    {
        float* sh = (float*)dyn;               // [8][256] scratch (W no longer needed)
        int r0 = bid * 8;
        for (int i = tid; i < 2048; i += BDIM) {
            int f = i & 255, rr = i >> 8;
            sh[rr * 256 + f] = g_h[(size_t)(r0 + rr) * LATD + f];
        }
        __syncthreads();
        int m = tid >> 5, o0 = (tid & 31) * 2;
        float s0 = 0.0f, s1 = 0.0f;
        #pragma unroll 4
        for (int k = 0; k < 256; k++) {
            float hv = sh[m * 256 + k];
            float2 w = *(const float2*)(W_out + (size_t)k * 64 + o0);
            s0 = fmaf(hv, w.x, s0);
            s1 = fmaf(hv, w.y, s1);
        }
        float2 o;
        o.x = s0 + b_out[o0];
        o.y = s1 + b_out[o0 + 1];
        *(float2*)(out + (size_t)(r0 + m) * 64 + o0) = o;
    }
}

extern "C" void kernel_launch(void* const* d_in, const int* in_sizes, int n_in,
                              void* d_out, int out_size)
{
    const float* x     = (const float*)d_in[0];
    const float* W_in  = (const float*)d_in[1];
    const float* b_in  = (const float*)d_in[2];
    const float* W1    = (const float*)d_in[3];
    const float* b1    = (const float*)d_in[4];
    const float* W2    = (const float*)d_in[5];
    const float* b2    = (const float*)d_in[6];
    const float* W_out = (const float*)d_in[7];
    const float* b_out = (const float*)d_in[8];

    static bool attr_done = false;
    if (!attr_done) {
        cudaFuncSetAttribute(ode_tc, cudaFuncAttributeMaxDynamicSharedMemorySize, (int)SMEM_TOTAL);
        attr_done = true;
    }
    ode_tc<<<NCTA, BDIM, SMEM_TOTAL>>>(x, W_in, b_in, W1, b1, W2, b2, W_out, b_out,
                                       (float*)d_out);
}